// round 5
// baseline (speedup 1.0000x reference)
#include <cuda_runtime.h>
#include <cuda_fp16.h>

#define N_NODES 50000
#define F_IN    16
#define N_HID   32
#define N_EDGES 1000000
#define EDGE_S  8
#define SROWS   9
#define BN_EPS  1e-3f
#define MSCALE  32.0f
#define MINV    0.03125f
// M layout per node: 384 B (3 aligned 128B lines).
//   bytes [0,128)   : s=0..3, byte s*32+o
//   bytes [128,256) : s=4..7
//   bytes [256,288) : s=8 (bias row), [288,384) pad

__device__ uint4 g_M4[N_NODES * 24];       // 19.2 MB fp8 table
__device__ float g_agg[N_NODES * N_HID];   // 6.4 MB (seeded with x@Wr+bc)
__device__ float g_pooled[N_HID];
__device__ unsigned int g_done;

// ---------------------------------------------------------------------------
// Fused precompute: M table (fp8 e4m3 * 32) + agg seed (x@W_root + b_conv).
// Warp = 4 nodes x 8 lanes; lane owns o-quad [4*oq, 4*oq+4) of its node.
// No shuffles; packing is 2x cvt + 1x STG.32 per s-row; seed is STG.128.
// ---------------------------------------------------------------------------
__global__ void __launch_bounds__(256) k_precompute(const float* __restrict__ x,
                                                    const float* __restrict__ Wk,
                                                    const float* __restrict__ bk,
                                                    const float* __restrict__ Wr,
                                                    const float* __restrict__ bc) {
    __shared__ float4 Wsh4[SROWS * F_IN * 8];   // 18 KB  [ (s*16+f)*8 + oq ]
    __shared__ float4 Wrsh4[F_IN * 8];          // 2 KB
    __shared__ float4 bcsh4[8];
    __shared__ float  xs[32 * F_IN];            // 2 KB
    int tid = threadIdx.x;

    float* Wshf = reinterpret_cast<float*>(Wsh4);
    for (int i = tid; i < EDGE_S * F_IN * N_HID; i += 256) Wshf[i] = Wk[i];
    for (int i = tid; i < F_IN * N_HID; i += 256) {
        Wshf[EDGE_S * F_IN * N_HID + i] = bk[i];
        reinterpret_cast<float*>(Wrsh4)[i] = Wr[i];
    }
    if (tid < 8) bcsh4[tid] = reinterpret_cast<const float4*>(bc)[tid];
    if (blockIdx.x == 0) {
        if (tid < N_HID) g_pooled[tid] = 0.f;
        if (tid == 32)   g_done = 0;
    }

    int w = tid >> 5, lane = tid & 31;
    int nl = lane >> 3, oq = lane & 7;
    unsigned int* M32 = reinterpret_cast<unsigned int*>(g_M4);

    for (int base = blockIdx.x * 32; base < N_NODES; base += gridDim.x * 32) {
        __syncthreads();
        for (int i = tid; i < 32 * F_IN; i += 256) {
            int gi = base * F_IN + i;
            xs[i] = (gi < N_NODES * F_IN) ? x[gi] : 0.f;
        }
        __syncthreads();

        int node = base + w * 4 + nl;
        bool valid = node < N_NODES;

        float xf[F_IN];
#pragma unroll
        for (int f = 0; f < F_IN; f++) xf[f] = xs[(w * 4 + nl) * F_IN + f];

#pragma unroll
        for (int s = 0; s < SROWS; s++) {
            float ax = 0.f, ay = 0.f, az = 0.f, aw = 0.f;
#pragma unroll
            for (int f = 0; f < F_IN; f++) {
                float4 wv = Wsh4[(s * F_IN + f) * 8 + oq];
                ax += xf[f] * wv.x; ay += xf[f] * wv.y;
                az += xf[f] * wv.z; aw += xf[f] * wv.w;
            }
            unsigned short lo, hi;
            asm("cvt.rn.satfinite.e4m3x2.f32 %0, %1, %2;"
                : "=h"(lo) : "f"(ay * MSCALE), "f"(ax * MSCALE));
            asm("cvt.rn.satfinite.e4m3x2.f32 %0, %1, %2;"
                : "=h"(hi) : "f"(aw * MSCALE), "f"(az * MSCALE));
            if (valid)
                M32[node * 96 + s * 8 + oq] =
                    (unsigned int)lo | ((unsigned int)hi << 16);
        }

        // agg seed = x @ W_root + b_conv  (STG.128, 4x128B per warp)
        float4 r = bcsh4[oq];
#pragma unroll
        for (int f = 0; f < F_IN; f++) {
            float4 wv = Wrsh4[f * 8 + oq];
            r.x += xf[f] * wv.x; r.y += xf[f] * wv.y;
            r.z += xf[f] * wv.z; r.w += xf[f] * wv.w;
        }
        if (valid)
            reinterpret_cast<float4*>(g_agg)[node * 8 + oq] = r;
    }
}

// ---------------------------------------------------------------------------
// Per-edge gather + scatter. 8 lanes/edge. Gather = 2x LDG.128 + 1x LDG.32,
// each touching exactly ONE 128B line per edge. xor-butterfly reduce in half2,
// lane g scatters chunk o = 16*(g&1) + 4*(g>>1) via red.global.add.v4.f32.
// ---------------------------------------------------------------------------
__device__ __forceinline__ __half2 cvt8(unsigned short v) {
    unsigned int h;
    asm("cvt.rn.f16x2.e4m3x2 %0, %1;" : "=r"(h) : "h"(v));
    return *reinterpret_cast<__half2*>(&h);
}

__global__ void __launch_bounds__(256) k_edge(const int* __restrict__ ei,
                                              const float* __restrict__ e) {
    int gtid = blockIdx.x * 256 + threadIdx.x;
    int edge = gtid >> 3;
    if (edge >= N_EDGES) return;
    int g     = threadIdx.x & 7;
    int lane  = threadIdx.x & 31;
    int gbase = lane & 24;
    int hidx  = g >> 1;

    int2 pe = reinterpret_cast<const int2*>(ei)[edge];
    int src = pe.x, tgt = pe.y;

    float ev  = e[edge * EDGE_S + g];
    float esA = __shfl_sync(0xffffffffu, ev, gbase + hidx);
    float esB = __shfl_sync(0xffffffffu, ev, gbase + 4 + hidx);
    __half2 eA = __float2half2_rn(esA);
    __half2 eB = __float2half2_rn(esB);

    const uint4* nb = g_M4 + src * 24;
    uint4 q0 = nb[g];        // s = g>>1,     o in [16*(g&1), +16)
    uint4 q1 = nb[8 + g];    // s = 4+(g>>1)

    __half2 r[8];
    {
        unsigned int wds[4] = {q0.x, q0.y, q0.z, q0.w};
#pragma unroll
        for (int w = 0; w < 4; w++) {
            r[2 * w]     = __hmul2(eA, cvt8((unsigned short)(wds[w] & 0xffffu)));
            r[2 * w + 1] = __hmul2(eA, cvt8((unsigned short)(wds[w] >> 16)));
        }
    }
    {
        unsigned int wds[4] = {q1.x, q1.y, q1.z, q1.w};
#pragma unroll
        for (int w = 0; w < 4; w++) {
            r[2 * w]     = __hfma2(eB, cvt8((unsigned short)(wds[w] & 0xffffu)), r[2 * w]);
            r[2 * w + 1] = __hfma2(eB, cvt8((unsigned short)(wds[w] >> 16)), r[2 * w + 1]);
        }
    }
#pragma unroll
    for (int j = 0; j < 8; j++) {
        unsigned int u = *reinterpret_cast<unsigned int*>(&r[j]);
        unsigned int v = __shfl_xor_sync(0xffffffffu, u, 2);
        r[j] = __hadd2(r[j], *reinterpret_cast<__half2*>(&v));
    }
#pragma unroll
    for (int j = 0; j < 8; j++) {
        unsigned int u = *reinterpret_cast<unsigned int*>(&r[j]);
        unsigned int v = __shfl_xor_sync(0xffffffffu, u, 4);
        r[j] = __hadd2(r[j], *reinterpret_cast<__half2*>(&v));
    }

    int ochunk = 16 * (g & 1) + 4 * hidx;
    __half2 c0, c1;
    if      (hidx == 0) { c0 = r[0]; c1 = r[1]; }
    else if (hidx == 1) { c0 = r[2]; c1 = r[3]; }
    else if (hidx == 2) { c0 = r[4]; c1 = r[5]; }
    else                { c0 = r[6]; c1 = r[7]; }

    unsigned int m8 = *reinterpret_cast<const unsigned int*>(
        reinterpret_cast<const char*>(nb) + 256 + ochunk);
    c0 = __hadd2(c0, cvt8((unsigned short)(m8 & 0xffffu)));
    c1 = __hadd2(c1, cvt8((unsigned short)(m8 >> 16)));

    float2 f0 = __half22float2(c0);
    float2 f1 = __half22float2(c1);
    float a0 = f0.x * MINV, a1 = f0.y * MINV;
    float a2 = f1.x * MINV, a3 = f1.y * MINV;

    float* dst = &g_agg[tgt * N_HID + ochunk];
    asm volatile("red.global.add.v4.f32 [%0], {%1, %2, %3, %4};"
                 :: "l"(dst), "f"(a0), "f"(a1), "f"(a2), "f"(a3) : "memory");
}

// ---------------------------------------------------------------------------
// h = BN(relu(agg)); pool; last block computes out = pooled@Wd + bd (fused).
// ---------------------------------------------------------------------------
__global__ void __launch_bounds__(256) k_node(const float* __restrict__ gamma,
                                              const float* __restrict__ beta,
                                              const float* __restrict__ mm,
                                              const float* __restrict__ mv,
                                              const float* __restrict__ Wd,
                                              const float* __restrict__ bd,
                                              float* __restrict__ out) {
    __shared__ float blk[N_HID];
    __shared__ int last;
    int tid = threadIdx.x;
    if (tid < N_HID) blk[tid] = 0.f;
    __syncthreads();

    int lane = tid & 31, w = tid >> 5;
    float scale = rsqrtf(mv[lane] + BN_EPS) * gamma[lane];
    float shift = beta[lane] - mm[lane] * scale;

    float pool = 0.f;
    int node = blockIdx.x * 8 + w;
    int stride = gridDim.x * 8;
    for (; node < N_NODES; node += stride) {
        float r = fmaxf(g_agg[node * N_HID + lane], 0.f);
        pool += r * scale + shift;
    }
    atomicAdd(&blk[lane], pool);
    __syncthreads();
    if (tid < N_HID) atomicAdd(&g_pooled[tid], blk[tid]);
    __threadfence();
    if (tid == 0)
        last = (atomicAdd(&g_done, 1u) == gridDim.x - 1) ? 1 : 0;
    __syncthreads();
    if (last) {
        if (tid < N_HID) blk[tid] = atomicAdd(&g_pooled[tid], 0.f);
        __syncthreads();
        if (tid < 3) {
            float acc = bd[tid];
#pragma unroll
            for (int o = 0; o < N_HID; o++)
                acc += blk[o] * Wd[o * 3 + tid];
            out[tid] = acc;
        }
    }
}

// ---------------------------------------------------------------------------
extern "C" void kernel_launch(void* const* d_in, const int* in_sizes, int n_in,
                              void* d_out, int out_size) {
    const float* x   = (const float*)d_in[0];
    const int*   ei  = (const int*)  d_in[1];
    const float* e   = (const float*)d_in[2];
    const float* Wk  = (const float*)d_in[3];
    const float* bk  = (const float*)d_in[4];
    const float* Wr  = (const float*)d_in[5];
    const float* bc  = (const float*)d_in[6];
    const float* ga  = (const float*)d_in[7];
    const float* be  = (const float*)d_in[8];
    const float* mm  = (const float*)d_in[9];
    const float* mv  = (const float*)d_in[10];
    const float* Wd  = (const float*)d_in[11];
    const float* bd  = (const float*)d_in[12];
    float* out = (float*)d_out;

    k_precompute<<<592, 256>>>(x, Wk, bk, Wr, bc);
    k_edge<<<(N_EDGES * 8 + 255) / 256, 256>>>(ei, e);
    k_node<<<592, 256>>>(ga, be, mm, mv, Wd, bd, out);
}

// round 6
// speedup vs baseline: 1.2010x; 1.2010x over previous
#include <cuda_runtime.h>
#include <cuda_fp16.h>

#define N_NODES 50000
#define F_IN    16
#define N_HID   32
#define N_EDGES 1000000
#define EDGE_S  8
#define SROWS   9
#define BN_EPS  1e-3f
#define MSCALE  32.0f
#define MINV    0.03125f
// M layout per node: 384 B (3 aligned 128B lines), bytes PERMUTED in o:
//   byte j of s-row holds channel o = pi(j) = (j>>1) + (j&1)*16.
//   bytes [0,128): s=0..3 | [128,256): s=4..7 | [256,288): s=8 bias | pad to 384.
// g_agg columns use the same permuted order; k_node/k_final un-permute via pi.

__device__ uint4 g_M4[N_NODES * 24];       // 19.2 MB fp8 table
__device__ float g_agg[N_NODES * N_HID];   // 6.4 MB (seeded with x@Wr+bc), perm cols
__device__ float g_pooled[N_HID];          // permuted order
__device__ unsigned int g_done;

// ---------------------------------------------------------------------------
// Precompute: M (fp8 e4m3 * 32, half2 o-paired math) + agg seed (fp32).
// Warp = 2 nodes x 16 lanes; lane i owns channels {i, i+16} = bytes {2i, 2i+1}.
// ---------------------------------------------------------------------------
__global__ void __launch_bounds__(256) k_precompute(const float* __restrict__ x,
                                                    const float* __restrict__ Wk,
                                                    const float* __restrict__ bk,
                                                    const float* __restrict__ Wr,
                                                    const float* __restrict__ bc) {
    // Wh[((s*8+fp)*16+i)*2 + (f&1)] = half2( W[s][f][i], W[s][f][i+16] )
    __shared__ unsigned int Wh[SROWS * F_IN * 16];   // 2304 u32 = 9.2 KB
    __shared__ float2 Wr2[F_IN * 16];                // 2 KB
    __shared__ float2 bc2[16];
    __shared__ float        xsf[16 * F_IN];          // 1 KB
    __shared__ unsigned int xsh[16 * F_IN];          // 1 KB (half2 dup)
    int tid = threadIdx.x;

    for (int idx = tid; idx < SROWS * F_IN * 16; idx += 256) {
        int i = idx & 15, f = (idx >> 4) & 15, s = idx >> 8;
        float lo = (s < EDGE_S) ? Wk[(s * F_IN + f) * N_HID + i]      : bk[f * N_HID + i];
        float hi = (s < EDGE_S) ? Wk[(s * F_IN + f) * N_HID + i + 16] : bk[f * N_HID + i + 16];
        int pos = ((s * 8 + (f >> 1)) * 16 + i) * 2 + (f & 1);
        __half2 h = __floats2half2_rn(lo, hi);
        Wh[pos] = *reinterpret_cast<unsigned int*>(&h);
    }
    if (tid < F_IN * 16) {
        int i = tid & 15, f = tid >> 4;
        Wr2[f * 16 + i] = make_float2(Wr[f * N_HID + i], Wr[f * N_HID + i + 16]);
    }
    if (tid < 16) bc2[tid] = make_float2(bc[tid], bc[tid + 16]);
    if (blockIdx.x == 0) {
        if (tid < N_HID) g_pooled[tid] = 0.f;
        if (tid == 32)   g_done = 0;
    }

    int w = tid >> 5, lane = tid & 31;
    int nl = lane >> 4, i = lane & 15;
    unsigned short* M16 = reinterpret_cast<unsigned short*>(g_M4);
    const __half2 msc = __floats2half2_rn(MSCALE, MSCALE);

    for (int base = blockIdx.x * 16; base < N_NODES; base += gridDim.x * 16) {
        __syncthreads();
        {   // stage 16 nodes of x (f32 + half2-dup), one LDG per thread
            int node = tid >> 4, f = tid & 15;
            int gi = (base + node) * F_IN + f;
            float v = (base + node < N_NODES) ? x[gi] : 0.f;
            xsf[tid] = v;
            __half2 hv = __half2half2(__float2half_rn(v));
            xsh[tid] = *reinterpret_cast<unsigned int*>(&hv);
        }
        __syncthreads();

        int node = base + w * 2 + nl;
        bool valid = node < N_NODES;
        int xb = (w * 2 + nl) * F_IN;

        unsigned int xf[F_IN];
#pragma unroll
        for (int f = 0; f < F_IN; f++) xf[f] = xsh[xb + f];

#pragma unroll
        for (int s = 0; s < SROWS; s++) {
            __half2 acc = __floats2half2_rn(0.f, 0.f);
#pragma unroll
            for (int fp = 0; fp < 8; fp++) {
                uint2 wv = *reinterpret_cast<const uint2*>(&Wh[((s * 8 + fp) * 16 + i) * 2]);
                acc = __hfma2(*reinterpret_cast<__half2*>(&xf[2 * fp]),
                              *reinterpret_cast<__half2*>(&wv.x), acc);
                acc = __hfma2(*reinterpret_cast<__half2*>(&xf[2 * fp + 1]),
                              *reinterpret_cast<__half2*>(&wv.y), acc);
            }
            acc = __hmul2(acc, msc);
            unsigned int av = *reinterpret_cast<unsigned int*>(&acc);
            unsigned short pk;
            asm("cvt.rn.satfinite.e4m3x2.f16x2 %0, %1;" : "=h"(pk) : "r"(av));
            if (valid) M16[node * 192 + s * 16 + i] = pk;
        }

        // agg seed (fp32): channels {i, i+16} -> permuted cols {2i, 2i+1}
        float2 r = bc2[i];
#pragma unroll
        for (int f = 0; f < F_IN; f++) {
            float xv = xsf[xb + f];
            float2 wv = Wr2[f * 16 + i];
            r.x += xv * wv.x; r.y += xv * wv.y;
        }
        if (valid)
            *reinterpret_cast<float2*>(&g_agg[node * N_HID + 2 * i]) = r;
    }
}

// ---------------------------------------------------------------------------
// Per-edge gather + scatter (UNCHANGED semantics; o-permutation transparent).
// 8 lanes/edge, 2x LDG.128 + 1x LDG.32 (1 line each), half2 butterfly,
// red.global.add.v4.f32 into permuted agg columns.
// ---------------------------------------------------------------------------
__device__ __forceinline__ __half2 cvt8(unsigned short v) {
    unsigned int h;
    asm("cvt.rn.f16x2.e4m3x2 %0, %1;" : "=r"(h) : "h"(v));
    return *reinterpret_cast<__half2*>(&h);
}

__global__ void __launch_bounds__(256) k_edge(const int* __restrict__ ei,
                                              const float* __restrict__ e) {
    int gtid = blockIdx.x * 256 + threadIdx.x;
    int edge = gtid >> 3;
    if (edge >= N_EDGES) return;
    int g     = threadIdx.x & 7;
    int lane  = threadIdx.x & 31;
    int gbase = lane & 24;
    int hidx  = g >> 1;

    int2 pe = reinterpret_cast<const int2*>(ei)[edge];
    int src = pe.x, tgt = pe.y;

    float ev  = e[edge * EDGE_S + g];
    float esA = __shfl_sync(0xffffffffu, ev, gbase + hidx);
    float esB = __shfl_sync(0xffffffffu, ev, gbase + 4 + hidx);
    __half2 eA = __float2half2_rn(esA);
    __half2 eB = __float2half2_rn(esB);

    const uint4* nb = g_M4 + src * 24;
    uint4 q0 = nb[g];
    uint4 q1 = nb[8 + g];

    __half2 r[8];
    {
        unsigned int wds[4] = {q0.x, q0.y, q0.z, q0.w};
#pragma unroll
        for (int w = 0; w < 4; w++) {
            r[2 * w]     = __hmul2(eA, cvt8((unsigned short)(wds[w] & 0xffffu)));
            r[2 * w + 1] = __hmul2(eA, cvt8((unsigned short)(wds[w] >> 16)));
        }
    }
    {
        unsigned int wds[4] = {q1.x, q1.y, q1.z, q1.w};
#pragma unroll
        for (int w = 0; w < 4; w++) {
            r[2 * w]     = __hfma2(eB, cvt8((unsigned short)(wds[w] & 0xffffu)), r[2 * w]);
            r[2 * w + 1] = __hfma2(eB, cvt8((unsigned short)(wds[w] >> 16)), r[2 * w + 1]);
        }
    }
#pragma unroll
    for (int j = 0; j < 8; j++) {
        unsigned int u = *reinterpret_cast<unsigned int*>(&r[j]);
        unsigned int v = __shfl_xor_sync(0xffffffffu, u, 2);
        r[j] = __hadd2(r[j], *reinterpret_cast<__half2*>(&v));
    }
#pragma unroll
    for (int j = 0; j < 8; j++) {
        unsigned int u = *reinterpret_cast<unsigned int*>(&r[j]);
        unsigned int v = __shfl_xor_sync(0xffffffffu, u, 4);
        r[j] = __hadd2(r[j], *reinterpret_cast<__half2*>(&v));
    }

    int ochunk = 16 * (g & 1) + 4 * hidx;
    __half2 c0, c1;
    if      (hidx == 0) { c0 = r[0]; c1 = r[1]; }
    else if (hidx == 1) { c0 = r[2]; c1 = r[3]; }
    else if (hidx == 2) { c0 = r[4]; c1 = r[5]; }
    else                { c0 = r[6]; c1 = r[7]; }

    unsigned int m8 = *reinterpret_cast<const unsigned int*>(
        reinterpret_cast<const char*>(nb) + 256 + ochunk);
    c0 = __hadd2(c0, cvt8((unsigned short)(m8 & 0xffffu)));
    c1 = __hadd2(c1, cvt8((unsigned short)(m8 >> 16)));

    float2 f0 = __half22float2(c0);
    float2 f1 = __half22float2(c1);
    float a0 = f0.x * MINV, a1 = f0.y * MINV;
    float a2 = f1.x * MINV, a3 = f1.y * MINV;

    float* dst = &g_agg[tgt * N_HID + ochunk];
    asm volatile("red.global.add.v4.f32 [%0], {%1, %2, %3, %4};"
                 :: "l"(dst), "f"(a0), "f"(a1), "f"(a2), "f"(a3) : "memory");
}

// ---------------------------------------------------------------------------
// h = BN(relu(agg)); pool; last block: out = pooled@Wd + bd.
// agg/pooled columns are permuted: channel o = pi(j) = (j>>1) + (j&1)*16.
// ---------------------------------------------------------------------------
__global__ void __launch_bounds__(256) k_node(const float* __restrict__ gamma,
                                              const float* __restrict__ beta,
                                              const float* __restrict__ mm,
                                              const float* __restrict__ mv,
                                              const float* __restrict__ Wd,
                                              const float* __restrict__ bd,
                                              float* __restrict__ out) {
    __shared__ float blk[N_HID];
    __shared__ int last;
    int tid = threadIdx.x;
    if (tid < N_HID) blk[tid] = 0.f;
    __syncthreads();

    int lane = tid & 31, w = tid >> 5;
    int o = (lane >> 1) + ((lane & 1) << 4);   // pi(lane)
    float scale = rsqrtf(mv[o] + BN_EPS) * gamma[o];
    float shift = beta[o] - mm[o] * scale;

    float pool = 0.f;
    int node = blockIdx.x * 8 + w;
    int stride = gridDim.x * 8;
    for (; node < N_NODES; node += stride) {
        float r = fmaxf(g_agg[node * N_HID + lane], 0.f);
        pool += r * scale + shift;
    }
    atomicAdd(&blk[lane], pool);
    __syncthreads();
    if (tid < N_HID) atomicAdd(&g_pooled[tid], blk[tid]);
    __threadfence();
    if (tid == 0)
        last = (atomicAdd(&g_done, 1u) == gridDim.x - 1) ? 1 : 0;
    __syncthreads();
    if (last) {
        if (tid < N_HID) blk[tid] = atomicAdd(&g_pooled[tid], 0.f);
        __syncthreads();
        if (tid < 3) {
            float acc = bd[tid];
#pragma unroll
            for (int j = 0; j < N_HID; j++) {
                int oj = (j >> 1) + ((j & 1) << 4);
                acc += blk[j] * Wd[oj * 3 + tid];
            }
            out[tid] = acc;
        }
    }
}

// ---------------------------------------------------------------------------
extern "C" void kernel_launch(void* const* d_in, const int* in_sizes, int n_in,
                              void* d_out, int out_size) {
    const float* x   = (const float*)d_in[0];
    const int*   ei  = (const int*)  d_in[1];
    const float* e   = (const float*)d_in[2];
    const float* Wk  = (const float*)d_in[3];
    const float* bk  = (const float*)d_in[4];
    const float* Wr  = (const float*)d_in[5];
    const float* bc  = (const float*)d_in[6];
    const float* ga  = (const float*)d_in[7];
    const float* be  = (const float*)d_in[8];
    const float* mm  = (const float*)d_in[9];
    const float* mv  = (const float*)d_in[10];
    const float* Wd  = (const float*)d_in[11];
    const float* bd  = (const float*)d_in[12];
    float* out = (float*)d_out;

    k_precompute<<<592, 256>>>(x, Wk, bk, Wr, bc);
    k_edge<<<(N_EDGES * 8 + 255) / 256, 256>>>(ei, e);
    k_node<<<592, 256>>>(ga, be, mm, mv, Wd, bd, out);
}

// round 7
// speedup vs baseline: 1.2966x; 1.0796x over previous
#include <cuda_runtime.h>
#include <cuda_fp16.h>

#define N_NODES 50000
#define F_IN    16
#define N_HID   32
#define N_EDGES 1000000
#define EDGE_S  8
#define SROWS   9
#define BN_EPS  1e-3f
#define MSCALE  32.0f
#define MINV    0.03125f
// M layout per node: 384 B (3 aligned 128B lines), bytes PERMUTED in o:
//   byte j of s-row holds channel o = pi(j) = (j>>1) + (j&1)*16.
//   bytes [0,128): s=0..3 | [128,256): s=4..7 | [256,288): s=8 bias | pad to 384.
// g_agg columns use the same permuted order; k_node/k_final un-permute via pi.

__device__ uint4 g_M4[N_NODES * 24];       // 19.2 MB fp8 table
__device__ float g_agg[N_NODES * N_HID];   // 6.4 MB (seeded with x@Wr+bc), perm cols
__device__ float g_pooled[N_HID];          // permuted order
__device__ unsigned int g_done;

// ---------------------------------------------------------------------------
// Precompute: M (fp8 e4m3 * 32, half2 o-paired math) + agg seed (fp32).
// Warp = 4 nodes; lane i (0..15) owns channels {i, i+16}; each lane processes
// TWO nodes so every W uint2 LDS is reused twice (halves crossbar traffic).
// ---------------------------------------------------------------------------
__global__ void __launch_bounds__(256) k_precompute(const float* __restrict__ x,
                                                    const float* __restrict__ Wk,
                                                    const float* __restrict__ bk,
                                                    const float* __restrict__ Wr,
                                                    const float* __restrict__ bc) {
    // Wh[((s*8+fp)*16+i)*2 + (f&1)] = half2( W[s][f][i], W[s][f][i+16] )
    __shared__ unsigned int Wh[SROWS * F_IN * 16];   // 9.2 KB
    __shared__ float2 Wr2[F_IN * 16];                // 2 KB
    __shared__ float2 bc2[16];
    __shared__ float        xsf[32 * F_IN];          // 2 KB
    __shared__ unsigned int xsh[32 * F_IN];          // 2 KB (half2 dup)
    int tid = threadIdx.x;

    for (int idx = tid; idx < SROWS * F_IN * 16; idx += 256) {
        int i = idx & 15, f = (idx >> 4) & 15, s = idx >> 8;
        float lo = (s < EDGE_S) ? Wk[(s * F_IN + f) * N_HID + i]      : bk[f * N_HID + i];
        float hi = (s < EDGE_S) ? Wk[(s * F_IN + f) * N_HID + i + 16] : bk[f * N_HID + i + 16];
        int pos = ((s * 8 + (f >> 1)) * 16 + i) * 2 + (f & 1);
        __half2 h = __floats2half2_rn(lo, hi);
        Wh[pos] = *reinterpret_cast<unsigned int*>(&h);
    }
    if (tid < F_IN * 16) {
        int i = tid & 15, f = tid >> 4;
        Wr2[f * 16 + i] = make_float2(Wr[f * N_HID + i], Wr[f * N_HID + i + 16]);
    }
    if (tid < 16) bc2[tid] = make_float2(bc[tid], bc[tid + 16]);
    if (blockIdx.x == 0) {
        if (tid < N_HID) g_pooled[tid] = 0.f;
        if (tid == 32)   g_done = 0;
    }

    int w = tid >> 5, lane = tid & 31;
    int nl = lane >> 4, i = lane & 15;
    unsigned short* M16 = reinterpret_cast<unsigned short*>(g_M4);
    const __half2 msc = __floats2half2_rn(MSCALE, MSCALE);

    for (int base = blockIdx.x * 32; base < N_NODES; base += gridDim.x * 32) {
        __syncthreads();
        for (int idx = tid; idx < 32 * F_IN; idx += 256) {
            int node = idx >> 4;
            int gi = (base + node) * F_IN + (idx & 15);
            float v = (base + node < N_NODES) ? x[gi] : 0.f;
            xsf[idx] = v;
            __half2 hv = __half2half2(__float2half_rn(v));
            xsh[idx] = *reinterpret_cast<unsigned int*>(&hv);
        }
        __syncthreads();

        int la = w * 4 + nl, lb = la + 2;          // two local nodes per lane
        int nodeA = base + la, nodeB = base + lb;
        bool vA = nodeA < N_NODES, vB = nodeB < N_NODES;

        unsigned int xfa[F_IN], xfb[F_IN];
#pragma unroll
        for (int f = 0; f < F_IN; f++) {
            xfa[f] = xsh[la * F_IN + f];
            xfb[f] = xsh[lb * F_IN + f];
        }

#pragma unroll
        for (int s = 0; s < SROWS; s++) {
            __half2 aA = __floats2half2_rn(0.f, 0.f);
            __half2 aB = __floats2half2_rn(0.f, 0.f);
#pragma unroll
            for (int fp = 0; fp < 8; fp++) {
                uint2 wv = *reinterpret_cast<const uint2*>(&Wh[((s * 8 + fp) * 16 + i) * 2]);
                __half2 w0 = *reinterpret_cast<__half2*>(&wv.x);
                __half2 w1 = *reinterpret_cast<__half2*>(&wv.y);
                aA = __hfma2(*reinterpret_cast<__half2*>(&xfa[2 * fp]),     w0, aA);
                aA = __hfma2(*reinterpret_cast<__half2*>(&xfa[2 * fp + 1]), w1, aA);
                aB = __hfma2(*reinterpret_cast<__half2*>(&xfb[2 * fp]),     w0, aB);
                aB = __hfma2(*reinterpret_cast<__half2*>(&xfb[2 * fp + 1]), w1, aB);
            }
            aA = __hmul2(aA, msc);
            aB = __hmul2(aB, msc);
            unsigned int uA = *reinterpret_cast<unsigned int*>(&aA);
            unsigned int uB = *reinterpret_cast<unsigned int*>(&aB);
            unsigned short pA, pB;
            asm("cvt.rn.satfinite.e4m3x2.f16x2 %0, %1;" : "=h"(pA) : "r"(uA));
            asm("cvt.rn.satfinite.e4m3x2.f16x2 %0, %1;" : "=h"(pB) : "r"(uB));
            if (vA) M16[nodeA * 192 + s * 16 + i] = pA;
            if (vB) M16[nodeB * 192 + s * 16 + i] = pB;
        }

        // agg seed (fp32): channels {i, i+16} -> permuted cols {2i, 2i+1}
        float2 rA = bc2[i], rB = bc2[i];
#pragma unroll
        for (int f = 0; f < F_IN; f++) {
            float2 wv = Wr2[f * 16 + i];
            float xa = xsf[la * F_IN + f];
            float xb = xsf[lb * F_IN + f];
            rA.x += xa * wv.x; rA.y += xa * wv.y;
            rB.x += xb * wv.x; rB.y += xb * wv.y;
        }
        if (vA) *reinterpret_cast<float2*>(&g_agg[nodeA * N_HID + 2 * i]) = rA;
        if (vB) *reinterpret_cast<float2*>(&g_agg[nodeB * N_HID + 2 * i]) = rB;
    }
}

// ---------------------------------------------------------------------------
// Per-edge gather + scatter (o-permutation transparent to byte-level math).
// 8 lanes/edge, 2x LDG.128 + 1x LDG.32 (1 line each), half2 butterfly,
// red.global.add.v4.f32 into permuted agg columns.
// ---------------------------------------------------------------------------
__device__ __forceinline__ __half2 cvt8(unsigned short v) {
    unsigned int h;
    asm("cvt.rn.f16x2.e4m3x2 %0, %1;" : "=r"(h) : "h"(v));
    return *reinterpret_cast<__half2*>(&h);
}

__global__ void __launch_bounds__(256) k_edge(const int* __restrict__ ei,
                                              const float* __restrict__ e) {
    int gtid = blockIdx.x * 256 + threadIdx.x;
    int edge = gtid >> 3;
    if (edge >= N_EDGES) return;
    int g     = threadIdx.x & 7;
    int lane  = threadIdx.x & 31;
    int gbase = lane & 24;
    int hidx  = g >> 1;

    int2 pe = reinterpret_cast<const int2*>(ei)[edge];
    int src = pe.x, tgt = pe.y;

    float ev  = e[edge * EDGE_S + g];
    float esA = __shfl_sync(0xffffffffu, ev, gbase + hidx);
    float esB = __shfl_sync(0xffffffffu, ev, gbase + 4 + hidx);
    __half2 eA = __float2half2_rn(esA);
    __half2 eB = __float2half2_rn(esB);

    const uint4* nb = g_M4 + src * 24;
    uint4 q0 = nb[g];
    uint4 q1 = nb[8 + g];

    __half2 r[8];
    {
        unsigned int wds[4] = {q0.x, q0.y, q0.z, q0.w};
#pragma unroll
        for (int w = 0; w < 4; w++) {
            r[2 * w]     = __hmul2(eA, cvt8((unsigned short)(wds[w] & 0xffffu)));
            r[2 * w + 1] = __hmul2(eA, cvt8((unsigned short)(wds[w] >> 16)));
        }
    }
    {
        unsigned int wds[4] = {q1.x, q1.y, q1.z, q1.w};
#pragma unroll
        for (int w = 0; w < 4; w++) {
            r[2 * w]     = __hfma2(eB, cvt8((unsigned short)(wds[w] & 0xffffu)), r[2 * w]);
            r[2 * w + 1] = __hfma2(eB, cvt8((unsigned short)(wds[w] >> 16)), r[2 * w + 1]);
        }
    }
#pragma unroll
    for (int j = 0; j < 8; j++) {
        unsigned int u = *reinterpret_cast<unsigned int*>(&r[j]);
        unsigned int v = __shfl_xor_sync(0xffffffffu, u, 2);
        r[j] = __hadd2(r[j], *reinterpret_cast<__half2*>(&v));
    }
#pragma unroll
    for (int j = 0; j < 8; j++) {
        unsigned int u = *reinterpret_cast<unsigned int*>(&r[j]);
        unsigned int v = __shfl_xor_sync(0xffffffffu, u, 4);
        r[j] = __hadd2(r[j], *reinterpret_cast<__half2*>(&v));
    }

    int ochunk = 16 * (g & 1) + 4 * hidx;
    __half2 c0, c1;
    if      (hidx == 0) { c0 = r[0]; c1 = r[1]; }
    else if (hidx == 1) { c0 = r[2]; c1 = r[3]; }
    else if (hidx == 2) { c0 = r[4]; c1 = r[5]; }
    else                { c0 = r[6]; c1 = r[7]; }

    unsigned int m8 = *reinterpret_cast<const unsigned int*>(
        reinterpret_cast<const char*>(nb) + 256 + ochunk);
    c0 = __hadd2(c0, cvt8((unsigned short)(m8 & 0xffffu)));
    c1 = __hadd2(c1, cvt8((unsigned short)(m8 >> 16)));

    float2 f0 = __half22float2(c0);
    float2 f1 = __half22float2(c1);
    float a0 = f0.x * MINV, a1 = f0.y * MINV;
    float a2 = f1.x * MINV, a3 = f1.y * MINV;

    float* dst = &g_agg[tgt * N_HID + ochunk];
    asm volatile("red.global.add.v4.f32 [%0], {%1, %2, %3, %4};"
                 :: "l"(dst), "f"(a0), "f"(a1), "f"(a2), "f"(a3) : "memory");
}

// ---------------------------------------------------------------------------
// h = BN(relu(agg)); pool; last block: out = pooled@Wd + bd.
// agg/pooled columns permuted: channel o = pi(j) = (j>>1) + (j&1)*16.
// ---------------------------------------------------------------------------
__global__ void __launch_bounds__(256) k_node(const float* __restrict__ gamma,
                                              const float* __restrict__ beta,
                                              const float* __restrict__ mm,
                                              const float* __restrict__ mv,
                                              const float* __restrict__ Wd,
                                              const float* __restrict__ bd,
                                              float* __restrict__ out) {
    __shared__ float blk[N_HID];
    __shared__ int last;
    int tid = threadIdx.x;
    if (tid < N_HID) blk[tid] = 0.f;
    __syncthreads();

    int lane = tid & 31, w = tid >> 5;
    int o = (lane >> 1) + ((lane & 1) << 4);   // pi(lane)
    float scale = rsqrtf(mv[o] + BN_EPS) * gamma[o];
    float shift = beta[o] - mm[o] * scale;

    float pool = 0.f;
    int node = blockIdx.x * 8 + w;
    int stride = gridDim.x * 8;
    for (; node < N_NODES; node += stride) {
        float r = fmaxf(g_agg[node * N_HID + lane], 0.f);
        pool += r * scale + shift;
    }
    atomicAdd(&blk[lane], pool);
    __syncthreads();
    if (tid < N_HID) atomicAdd(&g_pooled[tid], blk[tid]);
    __threadfence();
    if (tid == 0)
        last = (atomicAdd(&g_done, 1u) == gridDim.x - 1) ? 1 : 0;
    __syncthreads();
    if (last) {
        if (tid < N_HID) blk[tid] = atomicAdd(&g_pooled[tid], 0.f);
        __syncthreads();
        if (tid < 3) {
            float acc = bd[tid];
#pragma unroll
            for (int j = 0; j < N_HID; j++) {
                int oj = (j >> 1) + ((j & 1) << 4);
                acc += blk[j] * Wd[oj * 3 + tid];
            }
            out[tid] = acc;
        }
    }
}

// ---------------------------------------------------------------------------
extern "C" void kernel_launch(void* const* d_in, const int* in_sizes, int n_in,
                              void* d_out, int out_size) {
    const float* x   = (const float*)d_in[0];
    const int*   ei  = (const int*)  d_in[1];
    const float* e   = (const float*)d_in[2];
    const float* Wk  = (const float*)d_in[3];
    const float* bk  = (const float*)d_in[4];
    const float* Wr  = (const float*)d_in[5];
    const float* bc  = (const float*)d_in[6];
    const float* ga  = (const float*)d_in[7];
    const float* be  = (const float*)d_in[8];
    const float* mm  = (const float*)d_in[9];
    const float* mv  = (const float*)d_in[10];
    const float* Wd  = (const float*)d_in[11];
    const float* bd  = (const float*)d_in[12];
    float* out = (float*)d_out;

    k_precompute<<<592, 256>>>(x, Wk, bk, Wr, bc);
    k_edge<<<(N_EDGES * 8 + 255) / 256, 256>>>(ei, e);
    k_node<<<592, 256>>>(ga, be, mm, mv, Wd, bd, out);
}

// round 8
// speedup vs baseline: 1.5116x; 1.1658x over previous
#include <cuda_runtime.h>
#include <cuda_fp16.h>

#define N_NODES 50000
#define F_IN    16
#define N_HID   32
#define N_EDGES 1000000
#define EDGE_S  8
#define SROWS   9
#define BN_EPS  1e-3f
#define MSCALE  32.0f
#define MINV    0.03125f
// M layout per node: 384 B (3 aligned 128B lines), bytes PERMUTED in o:
//   byte j of s-row holds channel o = pi(j) = (j>>1) + (j&1)*16.
//   bytes [0,128): s=0..3 | [128,256): s=4..7 | [256,288): s=8 bias | pad to 384.
// M stores 32*M (scale folded in); g_agg carries 32x values; k_node divides.

__device__ uint4 g_M4[N_NODES * 24];       // 19.2 MB fp8 table
__device__ float g_agg[N_NODES * N_HID];   // 6.4 MB, perm cols, 32x scaled
__device__ float g_pooled[N_HID];          // permuted order
__device__ unsigned int g_done;

// ---------------------------------------------------------------------------
// Precompute: M = 32*(x@Wk | bk) as fp8 e4m3 (half2 o-paired), agg seed fp32.
// Warp = 4 nodes; lane i(0..15) owns channels {i,i+16}; 2 nodes per lane so
// each W uint4 LDS.128 is reused twice. W staged pre-scaled by 32.
// ---------------------------------------------------------------------------
__global__ void __launch_bounds__(256) k_precompute(const float* __restrict__ x,
                                                    const float* __restrict__ Wk,
                                                    const float* __restrict__ bk,
                                                    const float* __restrict__ Wr,
                                                    const float* __restrict__ bc) {
    // Wh[((s*4+fq)*16+i)*4 + (f&3)] = half2( 32*W[s][f][i], 32*W[s][f][i+16] )
    __shared__ unsigned int Wh[SROWS * F_IN * 16];   // 9.2 KB
    __shared__ float2 Wr2[F_IN * 16];                // 2 KB (x32 scaled)
    __shared__ float2 bc2[16];
    __shared__ float        xsf[32 * F_IN];          // 2 KB
    __shared__ unsigned int xsh[32 * F_IN];          // 2 KB (half2 dup)
    int tid = threadIdx.x;

    for (int idx = tid; idx < SROWS * F_IN * 16; idx += 256) {
        int i = idx & 15, f = (idx >> 4) & 15, s = idx >> 8;
        float lo = (s < EDGE_S) ? Wk[(s * F_IN + f) * N_HID + i]      : bk[f * N_HID + i];
        float hi = (s < EDGE_S) ? Wk[(s * F_IN + f) * N_HID + i + 16] : bk[f * N_HID + i + 16];
        int pos = ((s * 4 + (f >> 2)) * 16 + i) * 4 + (f & 3);
        __half2 h = __floats2half2_rn(lo * MSCALE, hi * MSCALE);
        Wh[pos] = *reinterpret_cast<unsigned int*>(&h);
    }
    if (tid < F_IN * 16) {
        int i = tid & 15, f = tid >> 4;
        Wr2[f * 16 + i] = make_float2(Wr[f * N_HID + i] * MSCALE,
                                      Wr[f * N_HID + i + 16] * MSCALE);
    }
    if (tid < 16) bc2[tid] = make_float2(bc[tid] * MSCALE, bc[tid + 16] * MSCALE);
    if (blockIdx.x == 0) {
        if (tid < N_HID) g_pooled[tid] = 0.f;
        if (tid == 32)   g_done = 0;
    }

    int w = tid >> 5, lane = tid & 31;
    int nl = lane >> 4, i = lane & 15;
    unsigned short* M16 = reinterpret_cast<unsigned short*>(g_M4);

    for (int base = blockIdx.x * 32; base < N_NODES; base += gridDim.x * 32) {
        __syncthreads();
        for (int idx = tid; idx < 32 * F_IN; idx += 256) {
            int node = idx >> 4;
            int gi = (base + node) * F_IN + (idx & 15);
            float v = (base + node < N_NODES) ? x[gi] : 0.f;
            xsf[idx] = v;
            __half2 hv = __half2half2(__float2half_rn(v));
            xsh[idx] = *reinterpret_cast<unsigned int*>(&hv);
        }
        __syncthreads();

        int la = w * 4 + nl, lb = la + 2;
        int nodeA = base + la, nodeB = base + lb;
        bool vA = nodeA < N_NODES, vB = nodeB < N_NODES;

        unsigned int xfa[F_IN], xfb[F_IN];
#pragma unroll
        for (int q = 0; q < 4; q++) {
            uint4 ta = *reinterpret_cast<const uint4*>(&xsh[la * F_IN + 4 * q]);
            uint4 tb = *reinterpret_cast<const uint4*>(&xsh[lb * F_IN + 4 * q]);
            xfa[4*q] = ta.x; xfa[4*q+1] = ta.y; xfa[4*q+2] = ta.z; xfa[4*q+3] = ta.w;
            xfb[4*q] = tb.x; xfb[4*q+1] = tb.y; xfb[4*q+2] = tb.z; xfb[4*q+3] = tb.w;
        }

#pragma unroll
        for (int s = 0; s < SROWS; s++) {
            __half2 aA = __floats2half2_rn(0.f, 0.f);
            __half2 aB = __floats2half2_rn(0.f, 0.f);
#pragma unroll
            for (int fq = 0; fq < 4; fq++) {
                uint4 wv = *reinterpret_cast<const uint4*>(&Wh[((s * 4 + fq) * 16 + i) * 4]);
                __half2 w0 = *reinterpret_cast<__half2*>(&wv.x);
                __half2 w1 = *reinterpret_cast<__half2*>(&wv.y);
                __half2 w2 = *reinterpret_cast<__half2*>(&wv.z);
                __half2 w3 = *reinterpret_cast<__half2*>(&wv.w);
                aA = __hfma2(*reinterpret_cast<__half2*>(&xfa[4*fq]),   w0, aA);
                aA = __hfma2(*reinterpret_cast<__half2*>(&xfa[4*fq+1]), w1, aA);
                aA = __hfma2(*reinterpret_cast<__half2*>(&xfa[4*fq+2]), w2, aA);
                aA = __hfma2(*reinterpret_cast<__half2*>(&xfa[4*fq+3]), w3, aA);
                aB = __hfma2(*reinterpret_cast<__half2*>(&xfb[4*fq]),   w0, aB);
                aB = __hfma2(*reinterpret_cast<__half2*>(&xfb[4*fq+1]), w1, aB);
                aB = __hfma2(*reinterpret_cast<__half2*>(&xfb[4*fq+2]), w2, aB);
                aB = __hfma2(*reinterpret_cast<__half2*>(&xfb[4*fq+3]), w3, aB);
            }
            unsigned int uA = *reinterpret_cast<unsigned int*>(&aA);
            unsigned int uB = *reinterpret_cast<unsigned int*>(&aB);
            unsigned short pA, pB;
            asm("cvt.rn.satfinite.e4m3x2.f16x2 %0, %1;" : "=h"(pA) : "r"(uA));
            asm("cvt.rn.satfinite.e4m3x2.f16x2 %0, %1;" : "=h"(pB) : "r"(uB));
            if (vA) M16[nodeA * 192 + s * 16 + i] = pA;
            if (vB) M16[nodeB * 192 + s * 16 + i] = pB;
        }

        float2 rA = bc2[i], rB = bc2[i];
#pragma unroll
        for (int f = 0; f < F_IN; f++) {
            float2 wv = Wr2[f * 16 + i];
            float xa = xsf[la * F_IN + f];
            float xb = xsf[lb * F_IN + f];
            rA.x += xa * wv.x; rA.y += xa * wv.y;
            rB.x += xb * wv.x; rB.y += xb * wv.y;
        }
        if (vA) *reinterpret_cast<float2*>(&g_agg[nodeA * N_HID + 2 * i]) = rA;
        if (vB) *reinterpret_cast<float2*>(&g_agg[nodeB * N_HID + 2 * i]) = rB;
    }
}

// ---------------------------------------------------------------------------
// Per-edge gather + scatter. 8 lanes/edge, 2x LDG.128 + 1x LDG.32 (1 line
// each). Reduce-scatter butterfly (keep-halving): answer lands in fixed regs.
// ---------------------------------------------------------------------------
__device__ __forceinline__ __half2 cvt8(unsigned int v) {
    unsigned int h;
    asm("cvt.rn.f16x2.e4m3x2 %0, %1;" : "=r"(h) : "h"((unsigned short)v));
    return *reinterpret_cast<__half2*>(&h);
}
__device__ __forceinline__ __half2 shx(__half2 v, int m) {
    unsigned int u = *reinterpret_cast<unsigned int*>(&v);
    u = __shfl_xor_sync(0xffffffffu, u, m);
    return *reinterpret_cast<__half2*>(&u);
}

__global__ void __launch_bounds__(256) k_edge(const int* __restrict__ ei,
                                              const float* __restrict__ e) {
    int gtid = blockIdx.x * 256 + threadIdx.x;
    int edge = gtid >> 3;
    if (edge >= N_EDGES) return;
    int g    = threadIdx.x & 7;
    int hidx = g >> 1;
    bool oddh = hidx & 1;
    bool odd2 = (hidx & 2) != 0;

    int2 pe = reinterpret_cast<const int2*>(ei)[edge];
    int src = pe.x, tgt = pe.y;

    __half2 eA = __float2half2_rn(e[edge * EDGE_S + hidx]);
    __half2 eB = __float2half2_rn(e[edge * EDGE_S + 4 + hidx]);

    const uint4* nb = g_M4 + src * 24;
    uint4 q0 = nb[g];        // s = hidx,   bytes [16*(g&1), +16)
    uint4 q1 = nb[8 + g];    // s = hidx+4

    __half2 r0 = __hmul2(eA, cvt8(q0.x)), r1 = __hmul2(eA, cvt8(q0.x >> 16));
    __half2 r2 = __hmul2(eA, cvt8(q0.y)), r3 = __hmul2(eA, cvt8(q0.y >> 16));
    __half2 r4 = __hmul2(eA, cvt8(q0.z)), r5 = __hmul2(eA, cvt8(q0.z >> 16));
    __half2 r6 = __hmul2(eA, cvt8(q0.w)), r7 = __hmul2(eA, cvt8(q0.w >> 16));
    r0 = __hfma2(eB, cvt8(q1.x), r0); r1 = __hfma2(eB, cvt8(q1.x >> 16), r1);
    r2 = __hfma2(eB, cvt8(q1.y), r2); r3 = __hfma2(eB, cvt8(q1.y >> 16), r3);
    r4 = __hfma2(eB, cvt8(q1.z), r4); r5 = __hfma2(eB, cvt8(q1.z >> 16), r5);
    r6 = __hfma2(eB, cvt8(q1.w), r6); r7 = __hfma2(eB, cvt8(q1.w >> 16), r7);

    // round 1 (xor 2): even-hidx keeps {r0,r1,r4,r5}, odd keeps {r2,r3,r6,r7}
    __half2 k0 = __hadd2(oddh ? r2 : r0, shx(oddh ? r0 : r2, 2));
    __half2 k1 = __hadd2(oddh ? r3 : r1, shx(oddh ? r1 : r3, 2));
    __half2 k2 = __hadd2(oddh ? r6 : r4, shx(oddh ? r4 : r6, 2));
    __half2 k3 = __hadd2(oddh ? r7 : r5, shx(oddh ? r5 : r7, 2));
    // round 2 (xor 4): low keeps {k0,k1}, high keeps {k2,k3}
    __half2 c0 = __hadd2(odd2 ? k2 : k0, shx(odd2 ? k0 : k2, 4));
    __half2 c1 = __hadd2(odd2 ? k3 : k1, shx(odd2 ? k1 : k3, 4));

    int ochunk = 16 * (g & 1) + 4 * hidx;
    unsigned int m8 = *reinterpret_cast<const unsigned int*>(
        reinterpret_cast<const char*>(nb) + 256 + ochunk);
    c0 = __hadd2(c0, cvt8(m8));
    c1 = __hadd2(c1, cvt8(m8 >> 16));

    float2 f0 = __half22float2(c0);
    float2 f1 = __half22float2(c1);

    float* dst = &g_agg[tgt * N_HID + ochunk];
    asm volatile("red.global.add.v4.f32 [%0], {%1, %2, %3, %4};"
                 :: "l"(dst), "f"(f0.x), "f"(f0.y), "f"(f1.x), "f"(f1.y) : "memory");
}

// ---------------------------------------------------------------------------
// h = BN(relu(agg/32)); pool; last block: out = pooled@Wd + bd.
// agg is 32x scaled -> fold /32 into BN scale. cols permuted via pi.
// ---------------------------------------------------------------------------
__global__ void __launch_bounds__(256) k_node(const float* __restrict__ gamma,
                                              const float* __restrict__ beta,
                                              const float* __restrict__ mm,
                                              const float* __restrict__ mv,
                                              const float* __restrict__ Wd,
                                              const float* __restrict__ bd,
                                              float* __restrict__ out) {
    __shared__ float blk[N_HID];
    __shared__ int last;
    int tid = threadIdx.x;
    if (tid < N_HID) blk[tid] = 0.f;
    __syncthreads();

    int lane = tid & 31, w = tid >> 5;
    int o = (lane >> 1) + ((lane & 1) << 4);   // pi(lane)
    float scale = rsqrtf(mv[o] + BN_EPS) * gamma[o] * MINV;
    float shift = beta[o] - mm[o] * rsqrtf(mv[o] + BN_EPS) * gamma[o];

    float pool = 0.f;
    int node = blockIdx.x * 8 + w;
    int stride = gridDim.x * 8;
    for (; node < N_NODES; node += stride) {
        float r = fmaxf(g_agg[node * N_HID + lane], 0.f);   // 32x scaled
        pool += r * scale + shift;
    }
    atomicAdd(&blk[lane], pool);
    __syncthreads();
    if (tid < N_HID) atomicAdd(&g_pooled[tid], blk[tid]);
    __threadfence();
    if (tid == 0)
        last = (atomicAdd(&g_done, 1u) == gridDim.x - 1) ? 1 : 0;
    __syncthreads();
    if (last) {
        if (tid < N_HID) blk[tid] = atomicAdd(&g_pooled[tid], 0.f);
        __syncthreads();
        if (tid < 3) {
            float acc = bd[tid];
#pragma unroll
            for (int j = 0; j < N_HID; j++) {
                int oj = (j >> 1) + ((j & 1) << 4);
                acc += blk[j] * Wd[oj * 3 + tid];
            }
            out[tid] = acc;
        }
    }
}

// ---------------------------------------------------------------------------
extern "C" void kernel_launch(void* const* d_in, const int* in_sizes, int n_in,
                              void* d_out, int out_size) {
    const float* x   = (const float*)d_in[0];
    const int*   ei  = (const int*)  d_in[1];
    const float* e   = (const float*)d_in[2];
    const float* Wk  = (const float*)d_in[3];
    const float* bk  = (const float*)d_in[4];
    const float* Wr  = (const float*)d_in[5];
    const float* bc  = (const float*)d_in[6];
    const float* ga  = (const float*)d_in[7];
    const float* be  = (const float*)d_in[8];
    const float* mm  = (const float*)d_in[9];
    const float* mv  = (const float*)d_in[10];
    const float* Wd  = (const float*)d_in[11];
    const float* bd  = (const float*)d_in[12];
    float* out = (float*)d_out;

    k_precompute<<<592, 256>>>(x, Wk, bk, Wr, bc);
    k_edge<<<(N_EDGES * 8 + 255) / 256, 256>>>(ei, e);
    k_node<<<592, 256>>>(ga, be, mm, mv, Wd, bd, out);
}

// round 9
// speedup vs baseline: 1.5595x; 1.0317x over previous
#include <cuda_runtime.h>
#include <cuda_fp16.h>

#define N_NODES 50000
#define F_IN    16
#define N_HID   32
#define N_EDGES 1000000
#define EDGE_S  8
#define SROWS   9
#define BN_EPS  1e-3f
#define MSCALE  32.0f
#define MINV    0.03125f
// M layout per node: 384 B (3 aligned 128B lines), bytes PERMUTED in o:
//   byte j of s-row holds channel o = pi(j) = (j>>1) + (j&1)*16.
//   bytes [0,128): s=0..3 | [128,256): s=4..7 | [256,288): s=8 bias | pad to 384.
// M stores 32*M; g_agg carries 32x values (perm cols); k_node folds /32 into BN.

__device__ uint4 g_M4[N_NODES * 24];       // 19.2 MB fp8 table
__device__ float g_agg[N_NODES * N_HID];   // 6.4 MB, perm cols, 32x scaled
__device__ float g_pooled[N_HID];          // permuted order
__device__ unsigned int g_done;

// ---------------------------------------------------------------------------
// Precompute: M = 32*(x@Wk | bk) fp8 e4m3 + agg seed = 32*(x@Wr)+32bc, all on
// the half2 o-paired pipeline. Warp = 4 nodes; lane i owns channels {i,i+16};
// 2 nodes/lane reuse every W uint4. Split accumulators halve chain depth.
// ---------------------------------------------------------------------------
__global__ void __launch_bounds__(256, 4) k_precompute(const float* __restrict__ x,
                                                       const float* __restrict__ Wk,
                                                       const float* __restrict__ bk,
                                                       const float* __restrict__ Wr,
                                                       const float* __restrict__ bc) {
    // Wh[((s*4+fq)*16+i)*4 + (f&3)] = half2( 32*W[s][f][i], 32*W[s][f][i+16] )
    __shared__ unsigned int Wh[SROWS * F_IN * 16];   // 9.2 KB
    __shared__ unsigned int Wrh[F_IN * 16];          // 1 KB, same layout (1 row)
    __shared__ float2 bc2[16];                       // 32x scaled
    __shared__ unsigned int xsh[32 * F_IN];          // 2 KB (half2 dup)
    int tid = threadIdx.x;

    for (int idx = tid; idx < SROWS * F_IN * 16; idx += 256) {
        int i = idx & 15, f = (idx >> 4) & 15, s = idx >> 8;
        float lo = (s < EDGE_S) ? Wk[(s * F_IN + f) * N_HID + i]      : bk[f * N_HID + i];
        float hi = (s < EDGE_S) ? Wk[(s * F_IN + f) * N_HID + i + 16] : bk[f * N_HID + i + 16];
        int pos = ((s * 4 + (f >> 2)) * 16 + i) * 4 + (f & 3);
        __half2 h = __floats2half2_rn(lo * MSCALE, hi * MSCALE);
        Wh[pos] = *reinterpret_cast<unsigned int*>(&h);
    }
    if (tid < F_IN * 16) {
        int i = tid & 15, f = tid >> 4;
        int pos = ((f >> 2) * 16 + i) * 4 + (f & 3);
        __half2 h = __floats2half2_rn(Wr[f * N_HID + i] * MSCALE,
                                      Wr[f * N_HID + i + 16] * MSCALE);
        Wrh[pos] = *reinterpret_cast<unsigned int*>(&h);
    }
    if (tid < 16) bc2[tid] = make_float2(bc[tid] * MSCALE, bc[tid + 16] * MSCALE);
    if (blockIdx.x == 0) {
        if (tid < N_HID) g_pooled[tid] = 0.f;
        if (tid == 32)   g_done = 0;
    }

    int w = tid >> 5, lane = tid & 31;
    int nl = lane >> 4, i = lane & 15;
    unsigned short* M16 = reinterpret_cast<unsigned short*>(g_M4);

    for (int base = blockIdx.x * 32; base < N_NODES; base += gridDim.x * 32) {
        __syncthreads();
        for (int idx = tid; idx < 32 * F_IN; idx += 256) {
            int node = idx >> 4;
            int gi = (base + node) * F_IN + (idx & 15);
            float v = (base + node < N_NODES) ? x[gi] : 0.f;
            __half2 hv = __half2half2(__float2half_rn(v));
            xsh[idx] = *reinterpret_cast<unsigned int*>(&hv);
        }
        __syncthreads();

        int la = w * 4 + nl, lb = la + 2;
        int nodeA = base + la, nodeB = base + lb;
        bool vA = nodeA < N_NODES, vB = nodeB < N_NODES;

        unsigned int xfa[F_IN], xfb[F_IN];
#pragma unroll
        for (int q = 0; q < 4; q++) {
            uint4 ta = *reinterpret_cast<const uint4*>(&xsh[la * F_IN + 4 * q]);
            uint4 tb = *reinterpret_cast<const uint4*>(&xsh[lb * F_IN + 4 * q]);
            xfa[4*q] = ta.x; xfa[4*q+1] = ta.y; xfa[4*q+2] = ta.z; xfa[4*q+3] = ta.w;
            xfb[4*q] = tb.x; xfb[4*q+1] = tb.y; xfb[4*q+2] = tb.z; xfb[4*q+3] = tb.w;
        }

#pragma unroll
        for (int s = 0; s < SROWS; s++) {
            __half2 aA0 = __floats2half2_rn(0.f, 0.f), aA1 = aA0;
            __half2 aB0 = aA0, aB1 = aA0;
#pragma unroll
            for (int fq = 0; fq < 4; fq++) {
                uint4 wv = *reinterpret_cast<const uint4*>(&Wh[((s * 4 + fq) * 16 + i) * 4]);
                __half2 w0 = *reinterpret_cast<__half2*>(&wv.x);
                __half2 w1 = *reinterpret_cast<__half2*>(&wv.y);
                __half2 w2 = *reinterpret_cast<__half2*>(&wv.z);
                __half2 w3 = *reinterpret_cast<__half2*>(&wv.w);
                __half2* accA = (fq & 1) ? &aA1 : &aA0;
                __half2* accB = (fq & 1) ? &aB1 : &aB0;
                *accA = __hfma2(*reinterpret_cast<__half2*>(&xfa[4*fq]),   w0, *accA);
                *accA = __hfma2(*reinterpret_cast<__half2*>(&xfa[4*fq+1]), w1, *accA);
                *accA = __hfma2(*reinterpret_cast<__half2*>(&xfa[4*fq+2]), w2, *accA);
                *accA = __hfma2(*reinterpret_cast<__half2*>(&xfa[4*fq+3]), w3, *accA);
                *accB = __hfma2(*reinterpret_cast<__half2*>(&xfb[4*fq]),   w0, *accB);
                *accB = __hfma2(*reinterpret_cast<__half2*>(&xfb[4*fq+1]), w1, *accB);
                *accB = __hfma2(*reinterpret_cast<__half2*>(&xfb[4*fq+2]), w2, *accB);
                *accB = __hfma2(*reinterpret_cast<__half2*>(&xfb[4*fq+3]), w3, *accB);
            }
            __half2 aA = __hadd2(aA0, aA1);
            __half2 aB = __hadd2(aB0, aB1);
            unsigned int uA = *reinterpret_cast<unsigned int*>(&aA);
            unsigned int uB = *reinterpret_cast<unsigned int*>(&aB);
            unsigned short pA, pB;
            asm("cvt.rn.satfinite.e4m3x2.f16x2 %0, %1;" : "=h"(pA) : "r"(uA));
            asm("cvt.rn.satfinite.e4m3x2.f16x2 %0, %1;" : "=h"(pB) : "r"(uB));
            if (vA) M16[nodeA * 192 + s * 16 + i] = pA;
            if (vB) M16[nodeB * 192 + s * 16 + i] = pB;
        }

        // agg seed on the same half2 pipeline (Wr row), fp32 only at the end
        {
            __half2 sA0 = __floats2half2_rn(0.f, 0.f), sA1 = sA0;
            __half2 sB0 = sA0, sB1 = sA0;
#pragma unroll
            for (int fq = 0; fq < 4; fq++) {
                uint4 wv = *reinterpret_cast<const uint4*>(&Wrh[(fq * 16 + i) * 4]);
                __half2 w0 = *reinterpret_cast<__half2*>(&wv.x);
                __half2 w1 = *reinterpret_cast<__half2*>(&wv.y);
                __half2 w2 = *reinterpret_cast<__half2*>(&wv.z);
                __half2 w3 = *reinterpret_cast<__half2*>(&wv.w);
                __half2* accA = (fq & 1) ? &sA1 : &sA0;
                __half2* accB = (fq & 1) ? &sB1 : &sB0;
                *accA = __hfma2(*reinterpret_cast<__half2*>(&xfa[4*fq]),   w0, *accA);
                *accA = __hfma2(*reinterpret_cast<__half2*>(&xfa[4*fq+1]), w1, *accA);
                *accA = __hfma2(*reinterpret_cast<__half2*>(&xfa[4*fq+2]), w2, *accA);
                *accA = __hfma2(*reinterpret_cast<__half2*>(&xfa[4*fq+3]), w3, *accA);
                *accB = __hfma2(*reinterpret_cast<__half2*>(&xfb[4*fq]),   w0, *accB);
                *accB = __hfma2(*reinterpret_cast<__half2*>(&xfb[4*fq+1]), w1, *accB);
                *accB = __hfma2(*reinterpret_cast<__half2*>(&xfb[4*fq+2]), w2, *accB);
                *accB = __hfma2(*reinterpret_cast<__half2*>(&xfb[4*fq+3]), w3, *accB);
            }
            float2 fA = __half22float2(__hadd2(sA0, sA1));
            float2 fB = __half22float2(__hadd2(sB0, sB1));
            float2 b = bc2[i];
            fA.x += b.x; fA.y += b.y;
            fB.x += b.x; fB.y += b.y;
            if (vA) *reinterpret_cast<float2*>(&g_agg[nodeA * N_HID + 2 * i]) = fA;
            if (vB) *reinterpret_cast<float2*>(&g_agg[nodeB * N_HID + 2 * i]) = fB;
        }
    }
}

// ---------------------------------------------------------------------------
// Per-edge gather + scatter. 8 lanes/edge, 2x LDG.128 + 1x LDG.32 (1 line
// each). Reduce-scatter butterfly; answer lands in fixed regs. At LTS cap.
// ---------------------------------------------------------------------------
__device__ __forceinline__ __half2 cvt8(unsigned int v) {
    unsigned int h;
    asm("cvt.rn.f16x2.e4m3x2 %0, %1;" : "=r"(h) : "h"((unsigned short)v));
    return *reinterpret_cast<__half2*>(&h);
}
__device__ __forceinline__ __half2 shx(__half2 v, int m) {
    unsigned int u = *reinterpret_cast<unsigned int*>(&v);
    u = __shfl_xor_sync(0xffffffffu, u, m);
    return *reinterpret_cast<__half2*>(&u);
}

__global__ void __launch_bounds__(256) k_edge(const int* __restrict__ ei,
                                              const float* __restrict__ e) {
    int gtid = blockIdx.x * 256 + threadIdx.x;
    int edge = gtid >> 3;
    if (edge >= N_EDGES) return;
    int g    = threadIdx.x & 7;
    int hidx = g >> 1;
    bool oddh = hidx & 1;
    bool odd2 = (hidx & 2) != 0;

    int2 pe = reinterpret_cast<const int2*>(ei)[edge];
    int src = pe.x, tgt = pe.y;

    __half2 eA = __float2half2_rn(e[edge * EDGE_S + hidx]);
    __half2 eB = __float2half2_rn(e[edge * EDGE_S + 4 + hidx]);

    const uint4* nb = g_M4 + src * 24;
    uint4 q0 = nb[g];        // s = hidx,   bytes [16*(g&1), +16)
    uint4 q1 = nb[8 + g];    // s = hidx+4

    __half2 r0 = __hmul2(eA, cvt8(q0.x)), r1 = __hmul2(eA, cvt8(q0.x >> 16));
    __half2 r2 = __hmul2(eA, cvt8(q0.y)), r3 = __hmul2(eA, cvt8(q0.y >> 16));
    __half2 r4 = __hmul2(eA, cvt8(q0.z)), r5 = __hmul2(eA, cvt8(q0.z >> 16));
    __half2 r6 = __hmul2(eA, cvt8(q0.w)), r7 = __hmul2(eA, cvt8(q0.w >> 16));
    r0 = __hfma2(eB, cvt8(q1.x), r0); r1 = __hfma2(eB, cvt8(q1.x >> 16), r1);
    r2 = __hfma2(eB, cvt8(q1.y), r2); r3 = __hfma2(eB, cvt8(q1.y >> 16), r3);
    r4 = __hfma2(eB, cvt8(q1.z), r4); r5 = __hfma2(eB, cvt8(q1.z >> 16), r5);
    r6 = __hfma2(eB, cvt8(q1.w), r6); r7 = __hfma2(eB, cvt8(q1.w >> 16), r7);

    __half2 k0 = __hadd2(oddh ? r2 : r0, shx(oddh ? r0 : r2, 2));
    __half2 k1 = __hadd2(oddh ? r3 : r1, shx(oddh ? r1 : r3, 2));
    __half2 k2 = __hadd2(oddh ? r6 : r4, shx(oddh ? r4 : r6, 2));
    __half2 k3 = __hadd2(oddh ? r7 : r5, shx(oddh ? r5 : r7, 2));
    __half2 c0 = __hadd2(odd2 ? k2 : k0, shx(odd2 ? k0 : k2, 4));
    __half2 c1 = __hadd2(odd2 ? k3 : k1, shx(odd2 ? k1 : k3, 4));

    int ochunk = 16 * (g & 1) + 4 * hidx;
    unsigned int m8 = *reinterpret_cast<const unsigned int*>(
        reinterpret_cast<const char*>(nb) + 256 + ochunk);
    c0 = __hadd2(c0, cvt8(m8));
    c1 = __hadd2(c1, cvt8(m8 >> 16));

    float2 f0 = __half22float2(c0);
    float2 f1 = __half22float2(c1);

    float* dst = &g_agg[tgt * N_HID + ochunk];
    asm volatile("red.global.add.v4.f32 [%0], {%1, %2, %3, %4};"
                 :: "l"(dst), "f"(f0.x), "f"(f0.y), "f"(f1.x), "f"(f1.y) : "memory");
}

// ---------------------------------------------------------------------------
// h = BN(relu(agg/32)); pool; last block: out = pooled@Wd + bd.
// ---------------------------------------------------------------------------
__global__ void __launch_bounds__(256) k_node(const float* __restrict__ gamma,
                                              const float* __restrict__ beta,
                                              const float* __restrict__ mm,
                                              const float* __restrict__ mv,
                                              const float* __restrict__ Wd,
                                              const float* __restrict__ bd,
                                              float* __restrict__ out) {
    __shared__ float blk[N_HID];
    __shared__ int last;
    int tid = threadIdx.x;
    if (tid < N_HID) blk[tid] = 0.f;
    __syncthreads();

    int lane = tid & 31, w = tid >> 5;
    int o = (lane >> 1) + ((lane & 1) << 4);   // pi(lane)
    float rs = rsqrtf(mv[o] + BN_EPS) * gamma[o];
    float scale = rs * MINV;
    float shift = beta[o] - mm[o] * rs;

    float pool = 0.f;
    int node = blockIdx.x * 8 + w;
    int stride = gridDim.x * 8;
    for (; node < N_NODES; node += stride) {
        float r = fmaxf(g_agg[node * N_HID + lane], 0.f);   // 32x scaled
        pool += r * scale + shift;
    }
    atomicAdd(&blk[lane], pool);
    __syncthreads();
    if (tid < N_HID) atomicAdd(&g_pooled[tid], blk[tid]);
    __threadfence();
    if (tid == 0)
        last = (atomicAdd(&g_done, 1u) == gridDim.x - 1) ? 1 : 0;
    __syncthreads();
    if (last) {
        if (tid < N_HID) blk[tid] = atomicAdd(&g_pooled[tid], 0.f);
        __syncthreads();
        if (tid < 3) {
            float acc = bd[tid];
#pragma unroll
            for (int j = 0; j < N_HID; j++) {
                int oj = (j >> 1) + ((j & 1) << 4);
                acc += blk[j] * Wd[oj * 3 + tid];
            }
            out[tid] = acc;
        }
    }
}

// ---------------------------------------------------------------------------
extern "C" void kernel_launch(void* const* d_in, const int* in_sizes, int n_in,
                              void* d_out, int out_size) {
    const float* x   = (const float*)d_in[0];
    const int*   ei  = (const int*)  d_in[1];
    const float* e   = (const float*)d_in[2];
    const float* Wk  = (const float*)d_in[3];
    const float* bk  = (const float*)d_in[4];
    const float* Wr  = (const float*)d_in[5];
    const float* bc  = (const float*)d_in[6];
    const float* ga  = (const float*)d_in[7];
    const float* be  = (const float*)d_in[8];
    const float* mm  = (const float*)d_in[9];
    const float* mv  = (const float*)d_in[10];
    const float* Wd  = (const float*)d_in[11];
    const float* bd  = (const float*)d_in[12];
    float* out = (float*)d_out;

    k_precompute<<<592, 256>>>(x, Wk, bk, Wr, bc);
    k_edge<<<(N_EDGES * 8 + 255) / 256, 256>>>(ei, e);
    k_node<<<592, 256>>>(ga, be, mm, mv, Wd, bd, out);
}

// round 10
// speedup vs baseline: 1.7345x; 1.1122x over previous
#include <cuda_runtime.h>
#include <cuda_fp16.h>
#include <cuda_bf16.h>

#define N_NODES 50000
#define F_IN    16
#define N_HID   32
#define N_EDGES 1000000
#define EDGE_S  8
#define SROWS   9
#define BN_EPS  1e-3f
#define MSCALE  32.0f
#define MINV    0.03125f
#define NTILES  (N_NODES / 16)     // 3125 exactly
// M layout per node: 384 B (3 aligned 128B lines), bytes PERMUTED in o:
//   byte j of s-row (32B at s*32) holds channel o = pi(j) = (j>>1) + (j&1)*16.
// M stores 32*M; g_agg carries 32x values (perm cols); k_node folds /32 into BN.

__device__ uint4 g_M4[N_NODES * 24];       // 19.2 MB fp8 table
__device__ float g_agg[N_NODES * N_HID];   // 6.4 MB, perm cols, 32x scaled
__device__ float g_pooled[N_HID];          // permuted order
__device__ unsigned int g_done;

__device__ __forceinline__ void mma_bf16(float d[4], const unsigned int a[4],
                                         unsigned int b0, unsigned int b1) {
    asm volatile(
        "mma.sync.aligned.m16n8k16.row.col.f32.bf16.bf16.f32 "
        "{%0,%1,%2,%3}, {%4,%5,%6,%7}, {%8,%9}, {%0,%1,%2,%3};"
        : "+f"(d[0]), "+f"(d[1]), "+f"(d[2]), "+f"(d[3])
        : "r"(a[0]), "r"(a[1]), "r"(a[2]), "r"(a[3]), "r"(b0), "r"(b1));
}
// byte0 = e4m3(lo), byte1 = e4m3(hi)
__device__ __forceinline__ unsigned int cvt2e4(float hi, float lo) {
    unsigned short p;
    asm("cvt.rn.satfinite.e4m3x2.f32 %0, %1, %2;" : "=h"(p) : "f"(hi), "f"(lo));
    return (unsigned int)p;
}
__device__ __forceinline__ unsigned int bf2(float lo, float hi) {
    __nv_bfloat162 h = __floats2bfloat162_rn(lo, hi);
    return *reinterpret_cast<unsigned int*>(&h);
}

// ---------------------------------------------------------------------------
// Tensor-core precompute. Warp = one 16-node tile. 10 N-groups (s=0..7 from
// Wk, s=8 from bk, group 9 = seed from Wr) x 4 n-tiles x mma.m16n8k16.
// B-frags (x32, bf16) staged per block. Table layout identical to previous
// rounds -> k_edge unchanged.
// ---------------------------------------------------------------------------
__global__ void __launch_bounds__(256) k_precompute(const float* __restrict__ x,
                                                    const float* __restrict__ Wk,
                                                    const float* __restrict__ bk,
                                                    const float* __restrict__ Wr,
                                                    const float* __restrict__ bc) {
    __shared__ uint2  Bf[10 * 4 * 32];   // [sg][nt][lane] = {b0b1, b2b3}
    __shared__ float4 bcp4[8];           // bc permuted, x32
    int tid = threadIdx.x;

    for (int idx = tid; idx < 10 * 4 * 32; idx += 256) {
        int l = idx & 31, nt = (idx >> 5) & 3, sg = idx >> 7;
        int t = l & 3, gid = l >> 2;
        int col = nt * 8 + gid;
        float v0, v1, v2, v3;
        if (sg < 8) {
            const float* Ws = Wk + sg * F_IN * N_HID;
            v0 = Ws[(2*t)   * N_HID + col]; v1 = Ws[(2*t+1) * N_HID + col];
            v2 = Ws[(2*t+8) * N_HID + col]; v3 = Ws[(2*t+9) * N_HID + col];
        } else {
            const float* Ws = (sg == 8) ? bk : Wr;
            v0 = Ws[(2*t)   * N_HID + col]; v1 = Ws[(2*t+1) * N_HID + col];
            v2 = Ws[(2*t+8) * N_HID + col]; v3 = Ws[(2*t+9) * N_HID + col];
        }
        Bf[idx] = make_uint2(bf2(v0 * MSCALE, v1 * MSCALE),
                             bf2(v2 * MSCALE, v3 * MSCALE));
    }
    if (tid < N_HID) {
        int o = (tid >> 1) + ((tid & 1) << 4);        // pi(tid)
        reinterpret_cast<float*>(bcp4)[tid] = bc[o] * MSCALE;
    }
    if (blockIdx.x == 0) {
        if (tid < N_HID) g_pooled[tid] = 0.f;
        if (tid == 32)   g_done = 0;
    }
    __syncthreads();

    int wid = tid >> 5, lane = tid & 31;
    int tile = blockIdx.x * 8 + wid;
    if (tile >= NTILES) return;
    int nb = tile * 16;
    int t = lane & 3, gr = lane >> 2;

    // A fragment: rows {gr, gr+8}, k-cols {2t,2t+1} and {2t+8,2t+9}
    const float2* xr0 = reinterpret_cast<const float2*>(x) + (nb + gr) * 8;
    const float2* xr1 = reinterpret_cast<const float2*>(x) + (nb + gr + 8) * 8;
    unsigned int a[4];
    { float2 v;
      v = xr0[t];     a[0] = bf2(v.x, v.y);
      v = xr1[t];     a[1] = bf2(v.x, v.y);
      v = xr0[t + 4]; a[2] = bf2(v.x, v.y);
      v = xr1[t + 4]; a[3] = bf2(v.x, v.y);
    }

    char* mbase = reinterpret_cast<char*>(g_M4);
#pragma unroll
    for (int sg = 0; sg < 9; sg++) {
        float d[4][4];
#pragma unroll
        for (int nt = 0; nt < 4; nt++) {
            d[nt][0] = d[nt][1] = d[nt][2] = d[nt][3] = 0.f;
            uint2 b = Bf[sg * 128 + nt * 32 + lane];
            mma_bf16(d[nt], a, b.x, b.y);
        }
        // row gr: bytes [4t,4t+4) = chs (2t, 2t+16, 2t+1, 2t+17)  (nt0/nt2)
        //         bytes [16+4t, +4) = chs (8+2t, 24+2t, 9+2t, 25+2t) (nt1/nt3)
        unsigned int w00 = (cvt2e4(d[2][1], d[0][1]) << 16) | cvt2e4(d[2][0], d[0][0]);
        unsigned int w01 = (cvt2e4(d[3][1], d[1][1]) << 16) | cvt2e4(d[3][0], d[1][0]);
        unsigned int w10 = (cvt2e4(d[2][3], d[0][3]) << 16) | cvt2e4(d[2][2], d[0][2]);
        unsigned int w11 = (cvt2e4(d[3][3], d[1][3]) << 16) | cvt2e4(d[3][2], d[1][2]);
        long off0 = (long)(nb + gr)     * 384 + sg * 32 + 4 * t;
        long off1 = (long)(nb + gr + 8) * 384 + sg * 32 + 4 * t;
        *reinterpret_cast<unsigned int*>(mbase + off0)      = w00;
        *reinterpret_cast<unsigned int*>(mbase + off0 + 16) = w01;
        *reinterpret_cast<unsigned int*>(mbase + off1)      = w10;
        *reinterpret_cast<unsigned int*>(mbase + off1 + 16) = w11;
    }
    // seed group (Wr): fp32 out + bc, permuted cols, 32x scaled
    {
        float d[4][4];
#pragma unroll
        for (int nt = 0; nt < 4; nt++) {
            d[nt][0] = d[nt][1] = d[nt][2] = d[nt][3] = 0.f;
            uint2 b = Bf[9 * 128 + nt * 32 + lane];
            mma_bf16(d[nt], a, b.x, b.y);
        }
        float4 bl = bcp4[t], bh = bcp4[4 + t];
        float4 v00 = make_float4(d[0][0] + bl.x, d[2][0] + bl.y, d[0][1] + bl.z, d[2][1] + bl.w);
        float4 v01 = make_float4(d[1][0] + bh.x, d[3][0] + bh.y, d[1][1] + bh.z, d[3][1] + bh.w);
        float4 v10 = make_float4(d[0][2] + bl.x, d[2][2] + bl.y, d[0][3] + bl.z, d[2][3] + bl.w);
        float4 v11 = make_float4(d[1][2] + bh.x, d[3][2] + bh.y, d[1][3] + bh.z, d[3][3] + bh.w);
        float4* ag = reinterpret_cast<float4*>(g_agg);
        ag[(nb + gr) * 8 + t]         = v00;
        ag[(nb + gr) * 8 + 4 + t]     = v01;
        ag[(nb + gr + 8) * 8 + t]     = v10;
        ag[(nb + gr + 8) * 8 + 4 + t] = v11;
    }
}

// ---------------------------------------------------------------------------
// Per-edge gather + scatter (UNCHANGED). 8 lanes/edge, 2x LDG.128 + 1x LDG.32,
// reduce-scatter butterfly, red.global.add.v4.f32. At LTS throughput cap.
// ---------------------------------------------------------------------------
__device__ __forceinline__ __half2 cvt8(unsigned int v) {
    unsigned int h;
    asm("cvt.rn.f16x2.e4m3x2 %0, %1;" : "=r"(h) : "h"((unsigned short)v));
    return *reinterpret_cast<__half2*>(&h);
}
__device__ __forceinline__ __half2 shx(__half2 v, int m) {
    unsigned int u = *reinterpret_cast<unsigned int*>(&v);
    u = __shfl_xor_sync(0xffffffffu, u, m);
    return *reinterpret_cast<__half2*>(&u);
}

__global__ void __launch_bounds__(256) k_edge(const int* __restrict__ ei,
                                              const float* __restrict__ e) {
    int gtid = blockIdx.x * 256 + threadIdx.x;
    int edge = gtid >> 3;
    if (edge >= N_EDGES) return;
    int g    = threadIdx.x & 7;
    int hidx = g >> 1;
    bool oddh = hidx & 1;
    bool odd2 = (hidx & 2) != 0;

    int2 pe = reinterpret_cast<const int2*>(ei)[edge];
    int src = pe.x, tgt = pe.y;

    __half2 eA = __float2half2_rn(e[edge * EDGE_S + hidx]);
    __half2 eB = __float2half2_rn(e[edge * EDGE_S + 4 + hidx]);

    const uint4* nb = g_M4 + src * 24;
    uint4 q0 = nb[g];
    uint4 q1 = nb[8 + g];

    __half2 r0 = __hmul2(eA, cvt8(q0.x)), r1 = __hmul2(eA, cvt8(q0.x >> 16));
    __half2 r2 = __hmul2(eA, cvt8(q0.y)), r3 = __hmul2(eA, cvt8(q0.y >> 16));
    __half2 r4 = __hmul2(eA, cvt8(q0.z)), r5 = __hmul2(eA, cvt8(q0.z >> 16));
    __half2 r6 = __hmul2(eA, cvt8(q0.w)), r7 = __hmul2(eA, cvt8(q0.w >> 16));
    r0 = __hfma2(eB, cvt8(q1.x), r0); r1 = __hfma2(eB, cvt8(q1.x >> 16), r1);
    r2 = __hfma2(eB, cvt8(q1.y), r2); r3 = __hfma2(eB, cvt8(q1.y >> 16), r3);
    r4 = __hfma2(eB, cvt8(q1.z), r4); r5 = __hfma2(eB, cvt8(q1.z >> 16), r5);
    r6 = __hfma2(eB, cvt8(q1.w), r6); r7 = __hfma2(eB, cvt8(q1.w >> 16), r7);

    __half2 k0 = __hadd2(oddh ? r2 : r0, shx(oddh ? r0 : r2, 2));
    __half2 k1 = __hadd2(oddh ? r3 : r1, shx(oddh ? r1 : r3, 2));
    __half2 k2 = __hadd2(oddh ? r6 : r4, shx(oddh ? r4 : r6, 2));
    __half2 k3 = __hadd2(oddh ? r7 : r5, shx(oddh ? r5 : r7, 2));
    __half2 c0 = __hadd2(odd2 ? k2 : k0, shx(odd2 ? k0 : k2, 4));
    __half2 c1 = __hadd2(odd2 ? k3 : k1, shx(odd2 ? k1 : k3, 4));

    int ochunk = 16 * (g & 1) + 4 * hidx;
    unsigned int m8 = *reinterpret_cast<const unsigned int*>(
        reinterpret_cast<const char*>(nb) + 256 + ochunk);
    c0 = __hadd2(c0, cvt8(m8));
    c1 = __hadd2(c1, cvt8(m8 >> 16));

    float2 f0 = __half22float2(c0);
    float2 f1 = __half22float2(c1);

    float* dst = &g_agg[tgt * N_HID + ochunk];
    asm volatile("red.global.add.v4.f32 [%0], {%1, %2, %3, %4};"
                 :: "l"(dst), "f"(f0.x), "f"(f0.y), "f"(f1.x), "f"(f1.y) : "memory");
}

// ---------------------------------------------------------------------------
// h = BN(relu(agg/32)); pool; last block: out = pooled@Wd + bd.
// float4 path: warp = 4 nodes/iter (LDG.128), xor-shuffle pool reduce.
// ---------------------------------------------------------------------------
__global__ void __launch_bounds__(256) k_node(const float* __restrict__ gamma,
                                              const float* __restrict__ beta,
                                              const float* __restrict__ mm,
                                              const float* __restrict__ mv,
                                              const float* __restrict__ Wd,
                                              const float* __restrict__ bd,
                                              float* __restrict__ out) {
    __shared__ float4 scl4[8], shf4[8];
    __shared__ float blk[N_HID];
    __shared__ int last;
    int tid = threadIdx.x;
    if (tid < N_HID) {
        blk[tid] = 0.f;
        int o = (tid >> 1) + ((tid & 1) << 4);        // pi(tid)
        float rs = rsqrtf(mv[o] + BN_EPS) * gamma[o];
        reinterpret_cast<float*>(scl4)[tid] = rs * MINV;
        reinterpret_cast<float*>(shf4)[tid] = beta[o] - mm[o] * rs;
    }
    __syncthreads();

    int lane = tid & 31, w = tid >> 5;
    int q = lane & 7, nsub = lane >> 3;
    float4 sc = scl4[q], sh = shf4[q];
    float4 pool = make_float4(0.f, 0.f, 0.f, 0.f);

    const float4* ag4 = reinterpret_cast<const float4*>(g_agg);
    for (int base = blockIdx.x * 32; base < N_NODES; base += gridDim.x * 32) {
        int node = base + w * 4 + nsub;
        if (node < N_NODES) {
            float4 v = ag4[node * 8 + q];
            pool.x += fmaxf(v.x, 0.f) * sc.x + sh.x;
            pool.y += fmaxf(v.y, 0.f) * sc.y + sh.y;
            pool.z += fmaxf(v.z, 0.f) * sc.z + sh.z;
            pool.w += fmaxf(v.w, 0.f) * sc.w + sh.w;
        }
    }
#pragma unroll
    for (int m = 8; m <= 16; m <<= 1) {
        pool.x += __shfl_xor_sync(0xffffffffu, pool.x, m);
        pool.y += __shfl_xor_sync(0xffffffffu, pool.y, m);
        pool.z += __shfl_xor_sync(0xffffffffu, pool.z, m);
        pool.w += __shfl_xor_sync(0xffffffffu, pool.w, m);
    }
    if (lane < 8) {
        atomicAdd(&blk[4 * lane + 0], pool.x);
        atomicAdd(&blk[4 * lane + 1], pool.y);
        atomicAdd(&blk[4 * lane + 2], pool.z);
        atomicAdd(&blk[4 * lane + 3], pool.w);
    }
    __syncthreads();
    if (tid < N_HID) atomicAdd(&g_pooled[tid], blk[tid]);
    __threadfence();
    if (tid == 0)
        last = (atomicAdd(&g_done, 1u) == gridDim.x - 1) ? 1 : 0;
    __syncthreads();
    if (last) {
        if (tid < N_HID) blk[tid] = atomicAdd(&g_pooled[tid], 0.f);
        __syncthreads();
        if (tid < 3) {
            float acc = bd[tid];
#pragma unroll
            for (int j = 0; j < N_HID; j++) {
                int oj = (j >> 1) + ((j & 1) << 4);
                acc += blk[j] * Wd[oj * 3 + tid];
            }
            out[tid] = acc;
        }
    }
}

// ---------------------------------------------------------------------------
extern "C" void kernel_launch(void* const* d_in, const int* in_sizes, int n_in,
                              void* d_out, int out_size) {
    const float* x   = (const float*)d_in[0];
    const int*   ei  = (const int*)  d_in[1];
    const float* e   = (const float*)d_in[2];
    const float* Wk  = (const float*)d_in[3];
    const float* bk  = (const float*)d_in[4];
    const float* Wr  = (const float*)d_in[5];
    const float* bc  = (const float*)d_in[6];
    const float* ga  = (const float*)d_in[7];
    const float* be  = (const float*)d_in[8];
    const float* mm  = (const float*)d_in[9];
    const float* mv  = (const float*)d_in[10];
    const float* Wd  = (const float*)d_in[11];
    const float* bd  = (const float*)d_in[12];
    float* out = (float*)d_out;

    k_precompute<<<(NTILES + 7) / 8, 256>>>(x, Wk, bk, Wr, bc);
    k_edge<<<(N_EDGES * 8 + 255) / 256, 256>>>(ei, e);
    k_node<<<592, 256>>>(ga, be, mm, mv, Wd, bd, out);
}